// round 3
// baseline (speedup 1.0000x reference)
#include <cuda_runtime.h>
#include <cuda_bf16.h>
#include <math.h>

#define NCH   256
#define OUTP  7
#define NSAMP 14            // OUT * SR
#define NPIX  49            // OUT * OUT
#define MP    1152          // max patch floats per channel (analysis bound ~1010)

__global__ __launch_bounds__(NCH)
void msroi_kernel(const float* __restrict__ f0,
                  const float* __restrict__ f1,
                  const float* __restrict__ f2,
                  const float* __restrict__ f3,
                  const float* __restrict__ boxes,
                  float* __restrict__ out,
                  int K)
{
    const int k    = blockIdx.x;
    const int tid  = threadIdx.x;
    const int warp = tid >> 5;
    const int lane = tid & 31;

    __shared__ float s_patch[8 * MP];
    __shared__ int   s_xl[NSAMP], s_yl[NSAMP];
    __shared__ float s_wx0[NSAMP], s_wx1[NSAMP];
    __shared__ float s_wy0[NSAMP], s_wy1[NSAMP];
    __shared__ int   s_xmin, s_ymin, s_pW, s_pH, s_fallback;

    // ---- roi params (uniform per block) ----
    const float bx1 = boxes[k * 4 + 0];
    const float by1 = boxes[k * 4 + 1];
    const float bx2 = boxes[k * 4 + 2];
    const float by2 = boxes[k * 4 + 3];

    const float area = fmaxf((bx2 - bx1) * (by2 - by1), 0.0f);
    const float s    = sqrtf(area);
    float lvlf = floorf(4.0f + log2f(s / 224.0f) + 1e-6f);
    lvlf = fminf(fmaxf(lvlf, 2.0f), 5.0f);
    const int lvl = (int)lvlf - 2;

    const float* feat;
    int H, W;
    float scale;
    if (lvl == 0)      { feat = f0; H = 200; W = 200; scale = 0.25f;    }
    else if (lvl == 1) { feat = f1; H = 100; W = 100; scale = 0.125f;   }
    else if (lvl == 2) { feat = f2; H = 50;  W = 50;  scale = 0.0625f;  }
    else               { feat = f3; H = 25;  W = 25;  scale = 0.03125f; }

    // ---- sample coordinates (14 x, 14 y), shared across channels ----
    if (tid < NSAMP) {
        const int i   = tid;
        const int p   = i >> 1;
        const int sub = i & 1;
        const float subofs = ((float)sub + 0.5f) * 0.5f;
        {
            const float x1 = bx1 * scale;
            const float x2 = bx2 * scale;
            const float roi_w = fmaxf(x2 - x1, 1.0f);
            const float bin_w = roi_w * (1.0f / OUTP);
            const float x  = x1 + (float)p * bin_w + subofs * bin_w;
            const float vx = (x >= -1.0f && x <= (float)W) ? 1.0f : 0.0f;
            const float xc = fminf(fmaxf(x, 0.0f), (float)(W - 1));
            const int   xl = (int)fminf(fmaxf(floorf(xc), 0.0f), (float)(W - 2));
            const float lx = xc - (float)xl;
            s_xl[i]  = xl;
            s_wx0[i] = (1.0f - lx) * vx;
            s_wx1[i] = lx * vx;
        }
        {
            const float y1 = by1 * scale;
            const float y2 = by2 * scale;
            const float roi_h = fmaxf(y2 - y1, 1.0f);
            const float bin_h = roi_h * (1.0f / OUTP);
            const float y  = y1 + (float)p * bin_h + subofs * bin_h;
            const float vy = (y >= -1.0f && y <= (float)H) ? 1.0f : 0.0f;
            const float yc = fminf(fmaxf(y, 0.0f), (float)(H - 1));
            const int   yl = (int)fminf(fmaxf(floorf(yc), 0.0f), (float)(H - 2));
            const float ly = yc - (float)yl;
            s_yl[i]  = yl;
            s_wy0[i] = (1.0f - ly) * vy;
            s_wy1[i] = ly * vy;
        }
    }
    __syncthreads();

    if (tid == 0) {
        int xmn = s_xl[0], xmx = s_xl[0], ymn = s_yl[0], ymx = s_yl[0];
        #pragma unroll
        for (int i = 1; i < NSAMP; i++) {
            xmn = min(xmn, s_xl[i]); xmx = max(xmx, s_xl[i]);
            ymn = min(ymn, s_yl[i]); ymx = max(ymx, s_yl[i]);
        }
        int pW = xmx - xmn + 2;     // +1 tap, +1 inclusive
        int pH = ymx - ymn + 2;
        int fb = (pW * pH > MP) ? 1 : 0;
        if (fb) { xmn = 0; ymn = 0; }
        s_xmin = xmn; s_ymin = ymn; s_pW = pW; s_pH = pH; s_fallback = fb;
        #pragma unroll
        for (int i = 0; i < NSAMP; i++) { s_xl[i] -= xmn; s_yl[i] -= ymn; }
    }
    __syncthreads();

    const int b = (k >= (K >> 1)) ? 1 : 0;
    const size_t HW = (size_t)H * W;

    if (!s_fallback) {
        const int pW = s_pW, pH = s_pH;
        const int xmin = s_xmin, ymin = s_ymin;
        float* __restrict__ P = s_patch + warp * MP;

        // preload this lane's (up to 2) sample descriptors into registers
        int   r_ya[2], r_yb[2], r_xa[2], r_xb[2];
        float r_wyA0[2], r_wyA1[2], r_wyB0[2], r_wyB1[2];
        float r_wx00[2], r_wx01[2], r_wx10[2], r_wx11[2];
        #pragma unroll
        for (int it = 0; it < 2; it++) {
            int sidx = lane + it * 32;
            int si = (sidx < NPIX) ? sidx : 0;
            int ph = si / OUTP;
            int pw = si - ph * OUTP;
            int iA = ph * 2, iB = ph * 2 + 1;
            int j0 = pw * 2, j1 = pw * 2 + 1;
            r_ya[it] = s_yl[iA]; r_yb[it] = s_yl[iB];
            r_xa[it] = s_xl[j0]; r_xb[it] = s_xl[j1];
            r_wyA0[it] = s_wy0[iA]; r_wyA1[it] = s_wy1[iA];
            r_wyB0[it] = s_wy0[iB]; r_wyB1[it] = s_wy1[iB];
            r_wx00[it] = s_wx0[j0]; r_wx01[it] = s_wx1[j0];
            r_wx10[it] = s_wx0[j1]; r_wx11[it] = s_wx1[j1];
        }

        for (int ch = warp; ch < NCH; ch += 8) {
            const float* __restrict__ src =
                feat + (size_t)(b * NCH + ch) * HW + (size_t)ymin * W + xmin;
            // stage patch (row-contiguous, coalesced)
            for (int r = 0; r < pH; r++) {
                const float* rp = src + (size_t)r * W;
                float*       sp = P + r * pW;
                for (int col = lane; col < pW; col += 32)
                    sp[col] = __ldg(rp + col);
            }
            __syncwarp();

            float* __restrict__ op = out + ((size_t)k * NCH + ch) * NPIX;
            #pragma unroll
            for (int it = 0; it < 2; it++) {
                const int sidx = lane + it * 32;
                if (sidx < NPIX) {
                    const float* rA0 = P + r_ya[it] * pW;
                    const float* rA1 = rA0 + pW;
                    const float* rB0 = P + r_yb[it] * pW;
                    const float* rB1 = rB0 + pW;
                    const int xa = r_xa[it], xb = r_xb[it];

                    float acc;
                    acc  = r_wyA0[it] * (r_wx00[it] * rA0[xa] + r_wx01[it] * rA0[xa + 1])
                         + r_wyA1[it] * (r_wx00[it] * rA1[xa] + r_wx01[it] * rA1[xa + 1]);
                    acc += r_wyA0[it] * (r_wx10[it] * rA0[xb] + r_wx11[it] * rA0[xb + 1])
                         + r_wyA1[it] * (r_wx10[it] * rA1[xb] + r_wx11[it] * rA1[xb + 1]);
                    acc += r_wyB0[it] * (r_wx00[it] * rB0[xa] + r_wx01[it] * rB0[xa + 1])
                         + r_wyB1[it] * (r_wx00[it] * rB1[xa] + r_wx01[it] * rB1[xa + 1]);
                    acc += r_wyB0[it] * (r_wx10[it] * rB0[xb] + r_wx11[it] * rB0[xb + 1])
                         + r_wyB1[it] * (r_wx10[it] * rB1[xb] + r_wx11[it] * rB1[xb + 1]);

                    op[sidx] = acc * 0.25f;
                }
            }
            __syncwarp();   // protect patch before next channel's stores
        }
    } else {
        // ---- fallback: direct global gather (thread = channel), patch too big ----
        const int c = tid;
        const float* __restrict__ base = feat + (size_t)(b * NCH + c) * HW;
        float* __restrict__ op = out + ((size_t)k * NCH + c) * NPIX;

        #pragma unroll
        for (int ph = 0; ph < OUTP; ph++) {
            const int iA = ph * 2, iB = ph * 2 + 1;
            const int   ylA = s_yl[iA],  ylB = s_yl[iB];
            const float wyA0 = s_wy0[iA], wyA1 = s_wy1[iA];
            const float wyB0 = s_wy0[iB], wyB1 = s_wy1[iB];
            const float* rA0 = base + (size_t)ylA * W;
            const float* rA1 = rA0 + W;
            const float* rB0 = base + (size_t)ylB * W;
            const float* rB1 = rB0 + W;

            #pragma unroll
            for (int pw = 0; pw < OUTP; pw++) {
                const int j0 = pw * 2, j1 = pw * 2 + 1;
                const int   xa = s_xl[j0],  xb = s_xl[j1];
                const float wx00 = s_wx0[j0], wx01 = s_wx1[j0];
                const float wx10 = s_wx0[j1], wx11 = s_wx1[j1];

                float acc;
                acc  = wyA0 * (wx00 * __ldg(rA0 + xa) + wx01 * __ldg(rA0 + xa + 1))
                     + wyA1 * (wx00 * __ldg(rA1 + xa) + wx01 * __ldg(rA1 + xa + 1));
                acc += wyA0 * (wx10 * __ldg(rA0 + xb) + wx11 * __ldg(rA0 + xb + 1))
                     + wyA1 * (wx10 * __ldg(rA1 + xb) + wx11 * __ldg(rA1 + xb + 1));
                acc += wyB0 * (wx00 * __ldg(rB0 + xa) + wx01 * __ldg(rB0 + xa + 1))
                     + wyB1 * (wx00 * __ldg(rB1 + xa) + wx01 * __ldg(rB1 + xa + 1));
                acc += wyB0 * (wx10 * __ldg(rB0 + xb) + wx11 * __ldg(rB0 + xb + 1))
                     + wyB1 * (wx10 * __ldg(rB1 + xb) + wx11 * __ldg(rB1 + xb + 1));

                op[ph * OUTP + pw] = acc * 0.25f;
            }
        }
    }
}

extern "C" void kernel_launch(void* const* d_in, const int* in_sizes, int n_in,
                              void* d_out, int out_size)
{
    const float* f0    = (const float*)d_in[0];
    const float* f1    = (const float*)d_in[1];
    const float* f2    = (const float*)d_in[2];
    const float* f3    = (const float*)d_in[3];
    const float* boxes = (const float*)d_in[4];
    const int K = in_sizes[4] / 4;   // 1024 rois

    msroi_kernel<<<K, NCH>>>(f0, f1, f2, f3, boxes, (float*)d_out, K);
}

// round 11
// speedup vs baseline: 5.6005x; 5.6005x over previous
#include <cuda_runtime.h>
#include <cuda_bf16.h>
#include <math.h>

#define NCH   256
#define OUTP  7
#define NSAMP 14            // OUT * SR
#define NPIX  49            // OUT * OUT

__global__ __launch_bounds__(NCH)
void msroi_kernel(const float* __restrict__ f0,
                  const float* __restrict__ f1,
                  const float* __restrict__ f2,
                  const float* __restrict__ f3,
                  const float* __restrict__ boxes,
                  float* __restrict__ out,
                  int K)
{
    const int k    = blockIdx.x;
    const int tid  = threadIdx.x;
    const int warp = tid >> 5;
    const int lane = tid & 31;

    __shared__ int   s_xl[NSAMP], s_yl[NSAMP];
    __shared__ float s_wx0[NSAMP], s_wx1[NSAMP];
    __shared__ float s_wy0[NSAMP], s_wy1[NSAMP];

    // ---- roi params (uniform per block) ----
    const float bx1 = boxes[k * 4 + 0];
    const float by1 = boxes[k * 4 + 1];
    const float bx2 = boxes[k * 4 + 2];
    const float by2 = boxes[k * 4 + 3];

    const float area = fmaxf((bx2 - bx1) * (by2 - by1), 0.0f);
    const float s    = sqrtf(area);
    float lvlf = floorf(4.0f + log2f(s / 224.0f) + 1e-6f);
    lvlf = fminf(fmaxf(lvlf, 2.0f), 5.0f);
    const int lvl = (int)lvlf - 2;

    const float* feat;
    int H, W;
    float scale;
    if (lvl == 0)      { feat = f0; H = 200; W = 200; scale = 0.25f;    }
    else if (lvl == 1) { feat = f1; H = 100; W = 100; scale = 0.125f;   }
    else if (lvl == 2) { feat = f2; H = 50;  W = 50;  scale = 0.0625f;  }
    else               { feat = f3; H = 25;  W = 25;  scale = 0.03125f; }

    // ---- sample coordinates (14 x, 14 y), shared across channels ----
    if (tid < NSAMP) {
        const int i   = tid;
        const int p   = i >> 1;
        const int sub = i & 1;
        const float subofs = ((float)sub + 0.5f) * 0.5f;
        {
            const float x1 = bx1 * scale;
            const float x2 = bx2 * scale;
            const float roi_w = fmaxf(x2 - x1, 1.0f);
            const float bin_w = roi_w * (1.0f / OUTP);
            const float x  = x1 + (float)p * bin_w + subofs * bin_w;
            const float vx = (x >= -1.0f && x <= (float)W) ? 1.0f : 0.0f;
            const float xc = fminf(fmaxf(x, 0.0f), (float)(W - 1));
            const int   xl = (int)fminf(fmaxf(floorf(xc), 0.0f), (float)(W - 2));
            const float lx = xc - (float)xl;
            s_xl[i]  = xl;
            s_wx0[i] = (1.0f - lx) * vx;
            s_wx1[i] = lx * vx;
        }
        {
            const float y1 = by1 * scale;
            const float y2 = by2 * scale;
            const float roi_h = fmaxf(y2 - y1, 1.0f);
            const float bin_h = roi_h * (1.0f / OUTP);
            const float y  = y1 + (float)p * bin_h + subofs * bin_h;
            const float vy = (y >= -1.0f && y <= (float)H) ? 1.0f : 0.0f;
            const float yc = fminf(fmaxf(y, 0.0f), (float)(H - 1));
            const int   yl = (int)fminf(fmaxf(floorf(yc), 0.0f), (float)(H - 2));
            const float ly = yc - (float)yl;
            s_yl[i]  = yl;
            s_wy0[i] = (1.0f - ly) * vy;
            s_wy1[i] = ly * vy;
        }
    }
    __syncthreads();

    // ---- per-lane precompute: 2 pixel batches (lane, lane+32), register resident ----
    int   oA0[2], oA1[2], oB0[2], oB1[2];   // row offsets (y*W) for the 4 rows
    int   xa[2], xb[2];
    float wyA0[2], wyA1[2], wyB0[2], wyB1[2];
    float wx00[2], wx01[2], wx10[2], wx11[2];
    #pragma unroll
    for (int it = 0; it < 2; it++) {
        const int sidx = lane + it * 32;
        const int si = (sidx < NPIX) ? sidx : 0;
        const int ph = si / OUTP;
        const int pw = si - ph * OUTP;
        const int iA = ph * 2, iB = ph * 2 + 1;
        const int j0 = pw * 2, j1 = pw * 2 + 1;
        const int yA = s_yl[iA], yB = s_yl[iB];
        oA0[it] = yA * W;       oA1[it] = yA * W + W;
        oB0[it] = yB * W;       oB1[it] = yB * W + W;
        xa[it]  = s_xl[j0];     xb[it]  = s_xl[j1];
        wyA0[it] = s_wy0[iA];   wyA1[it] = s_wy1[iA];
        wyB0[it] = s_wy0[iB];   wyB1[it] = s_wy1[iB];
        wx00[it] = s_wx0[j0];   wx01[it] = s_wx1[j0];
        wx10[it] = s_wx0[j1];   wx11[it] = s_wx1[j1];
    }

    const int b = (k >= (K >> 1)) ? 1 : 0;
    const size_t HW = (size_t)H * W;
    const float* __restrict__ fbase = feat + (size_t)(b * NCH) * HW;
    float* __restrict__ obase = out + (size_t)k * NCH * NPIX;

    // ---- hot loop: warp = channel, lanes = output pixels, direct global gather ----
    for (int ch = warp; ch < NCH; ch += 8) {
        const float* __restrict__ cb = fbase + (size_t)ch * HW;
        float* __restrict__ op = obase + (size_t)ch * NPIX;

        #pragma unroll
        for (int it = 0; it < 2; it++) {
            const int sidx = lane + it * 32;
            if (sidx < NPIX) {
                const float* rA0 = cb + oA0[it];
                const float* rA1 = cb + oA1[it];
                const float* rB0 = cb + oB0[it];
                const float* rB1 = cb + oB1[it];
                const int a = xa[it], bx = xb[it];

                const float gA00 = __ldg(rA0 + a);
                const float gA01 = __ldg(rA0 + a + 1);
                const float gA10 = __ldg(rA1 + a);
                const float gA11 = __ldg(rA1 + a + 1);
                const float gB00 = __ldg(rA0 + bx);
                const float gB01 = __ldg(rA0 + bx + 1);
                const float gB10 = __ldg(rA1 + bx);
                const float gB11 = __ldg(rA1 + bx + 1);
                const float gC00 = __ldg(rB0 + a);
                const float gC01 = __ldg(rB0 + a + 1);
                const float gC10 = __ldg(rB1 + a);
                const float gC11 = __ldg(rB1 + a + 1);
                const float gD00 = __ldg(rB0 + bx);
                const float gD01 = __ldg(rB0 + bx + 1);
                const float gD10 = __ldg(rB1 + bx);
                const float gD11 = __ldg(rB1 + bx + 1);

                float acc;
                acc  = wyA0[it] * (wx00[it] * gA00 + wx01[it] * gA01)
                     + wyA1[it] * (wx00[it] * gA10 + wx01[it] * gA11);
                acc += wyA0[it] * (wx10[it] * gB00 + wx11[it] * gB01)
                     + wyA1[it] * (wx10[it] * gB10 + wx11[it] * gB11);
                acc += wyB0[it] * (wx00[it] * gC00 + wx01[it] * gC01)
                     + wyB1[it] * (wx00[it] * gC10 + wx01[it] * gC11);
                acc += wyB0[it] * (wx10[it] * gD00 + wx11[it] * gD01)
                     + wyB1[it] * (wx10[it] * gD10 + wx11[it] * gD11);

                op[sidx] = acc * 0.25f;
            }
        }
    }
}

extern "C" void kernel_launch(void* const* d_in, const int* in_sizes, int n_in,
                              void* d_out, int out_size)
{
    const float* f0    = (const float*)d_in[0];
    const float* f1    = (const float*)d_in[1];
    const float* f2    = (const float*)d_in[2];
    const float* f3    = (const float*)d_in[3];
    const float* boxes = (const float*)d_in[4];
    const int K = in_sizes[4] / 4;   // 1024 rois

    msroi_kernel<<<K, NCH>>>(f0, f1, f2, f3, boxes, (float*)d_out, K);
}